// round 9
// baseline (speedup 1.0000x reference)
#include <cuda_runtime.h>
#include <math.h>

#define BB  4
#define NN  4096
#define NGG 4096
#define NUU 8192
#define KK  6

// ---------------- scratch (device globals; no allocation allowed) ----------
__device__ float4 g_ori4[BB*NN];
__device__ float4 g_norpre4[BB*NN];
__device__ float4 g_oripro4[BB*NN];
__device__ float4 g_norgt4[BB*NN];
__device__ unsigned long long g_amin[BB*NN];
__device__ unsigned long long g_knn[BB*NN*2*KK];
__device__ float g_rm_up_q[BB*NUU];
__device__ float g_rm_up_g[BB*NGG];
__device__ float g_rm_of_q[BB*NUU];
__device__ float g_rm_of_g[BB*NGG];
__device__ double g_acc[8];   // 0 loss_nor, 1 loss_nor_ori, 2 smooth, 3 lc, 4 lco

// ---------------- f32x2 helpers (sm_103a packed FMA) ------------------------
__device__ __forceinline__ unsigned long long pk2(float lo, float hi) {
    unsigned long long r;
    asm("mov.b64 %0,{%1,%2};" : "=l"(r) : "f"(lo), "f"(hi));
    return r;
}
__device__ __forceinline__ void upk2(unsigned long long v, float& lo, float& hi) {
    asm("mov.b64 {%0,%1},%2;" : "=f"(lo), "=f"(hi) : "l"(v));
}
__device__ __forceinline__ unsigned long long fma2(unsigned long long a,
                                                   unsigned long long b,
                                                   unsigned long long c) {
    unsigned long long d;
    asm("fma.rn.f32x2 %0,%1,%2,%3;" : "=l"(d) : "l"(a), "l"(b), "l"(c));
    return d;
}
__device__ __forceinline__ unsigned mono(float f) {
    unsigned u = __float_as_uint(f);
    return u ^ ((unsigned)((int)u >> 31) | 0x80000000u);
}

__device__ __forceinline__ double blockReduceSum(double v) {
    __shared__ double sh[32];
    __syncthreads();
    int lane = threadIdx.x & 31, w = threadIdx.x >> 5;
    #pragma unroll
    for (int o = 16; o; o >>= 1) v += __shfl_down_sync(0xffffffffu, v, o);
    if (lane == 0) sh[w] = v;
    __syncthreads();
    int nw = (blockDim.x + 31) >> 5;
    v = (threadIdx.x < nw) ? sh[threadIdx.x] : 0.0;
    if (w == 0) {
        #pragma unroll
        for (int o = 16; o; o >>= 1) v += __shfl_down_sync(0xffffffffu, v, o);
    }
    return v;
}

// ---------------- setup ------------------------------------------------------
__global__ void k_setup(const float* __restrict__ ori, const float* __restrict__ nor) {
    int i = blockIdx.x * blockDim.x + threadIdx.x;
    int stride = gridDim.x * blockDim.x;
    const float INF = __int_as_float(0x7f800000);
    for (int j = i; j < BB*NN; j += stride) g_amin[j] = ~0ull;
    for (int j = i; j < BB*NUU; j += stride) { g_rm_up_q[j] = INF; g_rm_of_q[j] = INF; }
    for (int j = i; j < BB*NGG; j += stride) { g_rm_up_g[j] = INF; g_rm_of_g[j] = INF; }
    if (i < 8) g_acc[i] = 0.0;
    if (i < BB*NN) {
        {
            float x = ori[3*i], y = ori[3*i+1], z = ori[3*i+2];
            float n = sqrtf(x*x + y*y + z*z + 1e-8f) + 1e-10f;
            g_ori4[i] = make_float4(x/n, y/n, z/n, 0.f);
        }
        {
            float x = nor[3*i], y = nor[3*i+1], z = nor[3*i+2];
            float n = sqrtf(x*x + y*y + z*z + 1e-8f) + 1e-10f;
            g_norpre4[i] = make_float4(x/n, y/n, z/n, 0.f);
        }
    }
}

// ---------------- fused heavy kernel segments -------------------------------
__device__ __forceinline__ void seg_knn(const float* __restrict__ pts,
                                        float4* s, int lbid) {
    int b   = lbid / 32;
    int rem = lbid % 32;
    int qc  = rem / 2;
    int ph  = rem % 2;
    for (int j = threadIdx.x; j < 2048; j += 256) {
        const float* tp = pts + (size_t)(b*NN + ph*2048 + j) * 3;
        float x = tp[0], y = tp[1], z = tp[2];
        s[j] = make_float4(-2.f*x, -2.f*y, -2.f*z, fmaf(x, x, fmaf(y, y, z*z)));
    }
    __syncthreads();
    int qi = qc*256 + threadIdx.x;
    const float* p = pts + (size_t)(b*NN + qi) * 3;
    float ax = p[0], ay = p[1], az = p[2];
    float bd[KK];
    int   bi[KK];
    #pragma unroll
    for (int k = 0; k < KK; k++) { bd[k] = 1e30f; bi[k] = 0; }
    #pragma unroll 4
    for (int j = 0; j < 2048; j++) {
        float4 T = s[j];
        float d = fmaf(ax, T.x, fmaf(ay, T.y, fmaf(az, T.z, T.w)));
        if (d < bd[KK-1]) {
            bd[KK-1] = d; bi[KK-1] = ph*2048 + j;
            #pragma unroll
            for (int k = KK-1; k > 0; k--) {
                if (bd[k] < bd[k-1]) {
                    float td = bd[k]; bd[k] = bd[k-1]; bd[k-1] = td;
                    int   ti = bi[k]; bi[k] = bi[k-1]; bi[k-1] = ti;
                }
            }
        }
    }
    unsigned long long* dst = g_knn + ((size_t)(b*NN + qi) * 2 + ph) * KK;
    #pragma unroll
    for (int k = 0; k < KK; k++)
        dst[k] = ((unsigned long long)mono(bd[k]) << 32) | (unsigned)bi[k];
}

// packed f32x2 chamfer: QPT=8, tile=1024, 256 thr
__device__ __forceinline__ void seg_chamfer(const float* __restrict__ q, int nq, int qs,
                                            const float* __restrict__ t, int nt, int ts,
                                            int tsplit, float* rowmin,
                                            char* smem, int lbid) {
    ulonglong2* sxy = (ulonglong2*)smem;            // (m2x,m2x),(m2y,m2y)
    ulonglong2* szs = (ulonglong2*)(smem + 16384);  // (m2z,m2z),(ss,ss)
    const int QPT = 8;
    int qpb = 256 * QPT;               // 2048 queries / block
    int qch = nq / qpb;
    int b   = lbid / (qch * tsplit);
    int rem = lbid % (qch * tsplit);
    int qc  = rem / tsplit;
    int tc  = rem % tsplit;
    int tile  = nt / tsplit;           // == 1024
    int tbase = tc * tile;
    for (int j = threadIdx.x; j < tile; j += 256) {
        const float* tp = t + (size_t)(b*nt + tbase + j) * ts;
        float x = tp[0], y = tp[1], z = tp[2];
        float m2x = -2.f*x, m2y = -2.f*y, m2z = -2.f*z;
        float ss = fmaf(x, x, fmaf(y, y, z*z));
        sxy[j] = make_ulonglong2(pk2(m2x, m2x), pk2(m2y, m2y));
        szs[j] = make_ulonglong2(pk2(m2z, m2z), pk2(ss, ss));
    }
    __syncthreads();
    int qbase = qc * qpb;
    float qx[QPT], qy[QPT], qz[QPT], mn[QPT];
    unsigned long long qx2[QPT/2], qy2[QPT/2], qz2[QPT/2];
    #pragma unroll
    for (int l = 0; l < QPT; l++) {
        int qi = qbase + l*256 + threadIdx.x;
        const float* qp = q + (size_t)(b*nq + qi) * qs;
        qx[l] = qp[0]; qy[l] = qp[1]; qz[l] = qp[2];
        mn[l] = 1e30f;
    }
    #pragma unroll
    for (int p = 0; p < QPT/2; p++) {
        qx2[p] = pk2(qx[2*p], qx[2*p+1]);
        qy2[p] = pk2(qy[2*p], qy[2*p+1]);
        qz2[p] = pk2(qz[2*p], qz[2*p+1]);
    }
    #pragma unroll 2
    for (int j = 0; j < tile; j++) {
        ulonglong2 A = sxy[j];
        ulonglong2 B = szs[j];
        #pragma unroll
        for (int p = 0; p < QPT/2; p++) {
            unsigned long long d = fma2(qz2[p], B.x, B.y);
            d = fma2(qy2[p], A.y, d);
            d = fma2(qx2[p], A.x, d);
            float dl, dh;
            upk2(d, dl, dh);
            mn[2*p]   = fminf(mn[2*p],   dl);
            mn[2*p+1] = fminf(mn[2*p+1], dh);
        }
    }
    #pragma unroll
    for (int l = 0; l < QPT; l++) {
        int qi = qbase + l*256 + threadIdx.x;
        float na = fmaf(qx[l], qx[l], fmaf(qy[l], qy[l], qz[l]*qz[l]));
        float v = fmaxf(mn[l] + na, 0.f);
        atomicMin((int*)&rowmin[b*nq + qi], __float_as_int(v));
    }
}

__device__ __forceinline__ void seg_argmin(const float* __restrict__ pts,
                                           const float* __restrict__ gt,
                                           float4* s, int lbid) {
    const int TS = 8, QCH = 4;
    int b   = lbid / (QCH*TS);
    int rem = lbid % (QCH*TS);
    int qc  = rem / TS;
    int tc  = rem % TS;
    int tbase = tc * 512;
    for (int j = threadIdx.x; j < 512; j += 256) {
        const float* gp = gt + (size_t)(b*NGG + tbase + j) * 6;
        float x = gp[0], y = gp[1], z = gp[2];
        s[j] = make_float4(-2.f*x, -2.f*y, -2.f*z, fmaf(x, x, fmaf(y, y, z*z)));
    }
    __syncthreads();
    float ax[4], ay[4], az[4], best[4];
    int bi[4];
    int qbase = qc * 1024;
    #pragma unroll
    for (int l = 0; l < 4; l++) {
        int qi = qbase + l*256 + threadIdx.x;
        const float* p = pts + (size_t)(b*NN + qi) * 3;
        ax[l] = p[0]; ay[l] = p[1]; az[l] = p[2];
        best[l] = 1e30f; bi[l] = 0;
    }
    #pragma unroll 2
    for (int j = 0; j < 512; j++) {
        float4 T = s[j];
        #pragma unroll
        for (int l = 0; l < 4; l++) {
            float d = fmaf(ax[l], T.x, fmaf(ay[l], T.y, fmaf(az[l], T.z, T.w)));
            if (d < best[l]) { best[l] = d; bi[l] = tbase + j; }
        }
    }
    #pragma unroll
    for (int l = 0; l < 4; l++) {
        int qi = qbase + l*256 + threadIdx.x;
        unsigned long long k = ((unsigned long long)mono(best[l]) << 32) | (unsigned)bi[l];
        atomicMin(&g_amin[b*NN + qi], k);
    }
}

// 512 blocks. Type-striped bid mapping for per-SM load balance:
//   odd bid  -> chamfer (256 blocks: kind = (bid>>1)&3, lbid = bid>>3)
//   even bid -> knn / argmin alternating (128 each)
__global__ void __launch_bounds__(256) k_heavy(const float* __restrict__ pts,
                                               const float* __restrict__ gt,
                                               const float* __restrict__ up,
                                               const float* __restrict__ off) {
    __shared__ char smem[32768];
    int bid = blockIdx.x;
    if (bid & 1) {
        int c = bid >> 1;            // 0..255
        int kind = c & 3;            // stripe chamfer kinds too
        int lbid = c >> 2;           // 0..63
        if (kind == 0)      seg_chamfer(up,  NUU, 3, gt,  NGG, 6, 4, g_rm_up_q, smem, lbid);
        else if (kind == 1) seg_chamfer(gt,  NGG, 6, up,  NUU, 3, 8, g_rm_up_g, smem, lbid);
        else if (kind == 2) seg_chamfer(off, NUU, 3, gt,  NGG, 6, 4, g_rm_of_q, smem, lbid);
        else                seg_chamfer(gt,  NGG, 6, off, NUU, 3, 8, g_rm_of_g, smem, lbid);
    } else {
        int c = bid >> 1;            // 0..255
        if (c & 1) seg_argmin(pts, gt, (float4*)smem, c >> 1);   // 0..127
        else       seg_knn(pts, (float4*)smem, c >> 1);          // 0..127
    }
}

// per-point: gather normal, projection, loss_nor / loss_nor_ori terms
__global__ void k_post(const float* __restrict__ gt) {
    int i = blockIdx.x * blockDim.x + threadIdx.x;
    int b = i / NN;
    unsigned gidx = (unsigned)(g_amin[i] & 0xffffffffu);
    const float* gp = gt + (size_t)(b*NGG + gidx) * 6;
    float gx = gp[3], gy = gp[4], gz = gp[5];
    float4 o = g_ori4[i];
    float dn = fmaf(o.x, gx, fmaf(o.y, gy, o.z*gz));
    float vx = o.x - gx*dn, vy = o.y - gy*dn, vz = o.z - gz*dn;
    float nv = sqrtf(fmaf(vx, vx, fmaf(vy, vy, vz*vz)) + 1e-8f) + 1e-10f;
    g_oripro4[i] = make_float4(vx/nv, vy/nv, vz/nv, 0.f);
    g_norgt4[i]  = make_float4(gx, gy, gz, 0.f);
    float4 p = g_norpre4[i];
    float dpn = fmaf(gx, p.x, fmaf(gy, p.y, gz*p.z));
    float na = fmaxf(sqrtf(fmaf(gx, gx, fmaf(gy, gy, gz*gz))), 1e-8f);
    float nb = fmaxf(sqrtf(fmaf(p.x, p.x, fmaf(p.y, p.y, p.z*p.z))), 1e-8f);
    double t_nor = 1.0 - (double)fabsf(dpn / (na*nb));
    double t_ori = (double)fabsf(dn);
    double s1 = blockReduceSum(t_nor);
    double s2 = blockReduceSum(t_ori);
    if (threadIdx.x == 0) {
        atomicAdd(&g_acc[0], s1);
        atomicAdd(&g_acc[1], s2);
    }
}

// blocks [0,64): smoothness; blocks [64,128): weighted rowmin reduction
__global__ void k_smooth() {
    int bid = blockIdx.x;
    if (bid < 64) {
        int i = bid * blockDim.x + threadIdx.x;     // 0..16383
        int b = i / NN;
        unsigned long long a[2*KK];
        const unsigned long long* src = g_knn + (size_t)i * 2 * KK;
        #pragma unroll
        for (int k = 0; k < 2*KK; k++) a[k] = src[k];
        #pragma unroll
        for (int k = 1; k < 2*KK; k++) {
            unsigned long long v = a[k];
            int m = k;
            while (m > 0 && a[m-1] > v) { a[m] = a[m-1]; m--; }
            a[m] = v;
        }
        int base = b*NN;
        float4 P = g_oripro4[i];
        float4 G = g_norgt4[i];
        float Rx = P.y*G.z - P.z*G.y;
        float Ry = P.z*G.x - P.x*G.z;
        float Rz = P.x*G.y - P.y*G.x;
        float nP = fmaxf(sqrtf(fmaf(P.x, P.x, fmaf(P.y, P.y, P.z*P.z))), 1e-8f);
        float nR = fmaxf(sqrtf(fmaf(Rx, Rx, fmaf(Ry, Ry, Rz*Rz))), 1e-8f);
        double sum = 0.0;
        #pragma unroll
        for (int k = 0; k < KK; k++) {
            int ni = (int)(unsigned)(a[k] & 0xffffffffu);
            float4 go = g_oripro4[base + ni];
            float4 gn = g_norgt4[base + ni];
            float dnn = fmaf(gn.x, G.x, fmaf(gn.y, G.y, gn.z*G.z));
            float ndv = expf(-dnn / 0.3f) * 10.f + 1.f;
            float w = (ndv < 4.f) ? 1.f : 5.f;
            float ngo = fmaxf(sqrtf(fmaf(go.x, go.x, fmaf(go.y, go.y, go.z*go.z))), 1e-8f);
            float c0 = fmaf(go.x, P.x, fmaf(go.y, P.y, go.z*P.z)) / (ngo*nP);
            float c1 = fmaf(go.x, Rx, fmaf(go.y, Ry, go.z*Rz)) / (ngo*nR);
            float c = fminf(1.f - fabsf(c0), 1.f - fabsf(c1));
            sum += (double)(w * c);
        }
        double tot = blockReduceSum(sum);
        if (threadIdx.x == 0) atomicAdd(&g_acc[2], tot);
    } else {
        int i = (bid - 64) * blockDim.x + threadIdx.x;   // 0..16383
        const double wq = 1.0 / (double)(BB*NUU);
        const double wg = 1.0 / (double)(BB*NGG);
        double lc = 0.0, lco = 0.0;
        lc  += wq * ((double)g_rm_up_q[i] + (double)g_rm_up_q[i + 16384]);
        lc  += wg * (double)g_rm_up_g[i];
        lco += wq * ((double)g_rm_of_q[i] + (double)g_rm_of_q[i + 16384]);
        lco += wg * (double)g_rm_of_g[i];
        double s1 = blockReduceSum(lc);
        double s2 = blockReduceSum(lco);
        if (threadIdx.x == 0) {
            atomicAdd(&g_acc[3], s1);
            atomicAdd(&g_acc[4], s2);
        }
    }
}

__global__ void k_final(float* __restrict__ out) {
    if (threadIdx.x == 0) {
        double loss_nor     = g_acc[0] / (double)(BB*NN);
        double loss_nor_ori = g_acc[1] / (double)(BB*NN);
        double loss_smooth  = g_acc[2] / (double)(BB*NN*KK);
        double lc  = g_acc[3];
        double lco = g_acc[4];
        double loss_cd = lc + 0.4 * lco;
        double loss = loss_smooth + loss_nor + 0.1 * loss_nor_ori + 200.0 * loss_cd;
        out[0] = (float)loss;
        out[1] = (float)loss_smooth;
        out[2] = (float)loss_nor;
        out[3] = (float)lco;
        out[4] = (float)loss_nor_ori;
        out[5] = (float)lc;
        out[6] = (float)lc;
    }
}

// ---------------- launch ----------------------------------------------------
extern "C" void kernel_launch(void* const* d_in, const int* in_sizes, int n_in,
                              void* d_out, int out_size) {
    const float* ori = (const float*)d_in[0];
    const float* nor = (const float*)d_in[1];
    const float* up  = (const float*)d_in[2];
    const float* off = (const float*)d_in[3];
    const float* pts = (const float*)d_in[4];
    const float* gt  = (const float*)d_in[5];
    float* out = (float*)d_out;

    k_setup<<<64, 256>>>(ori, nor);
    k_heavy<<<512, 256>>>(pts, gt, up, off);
    k_post<<<64, 256>>>(gt);
    k_smooth<<<128, 256>>>();
    k_final<<<1, 32>>>(out);
}

// round 10
// speedup vs baseline: 1.5837x; 1.5837x over previous
#include <cuda_runtime.h>
#include <math.h>

#define BB  4
#define NN  4096
#define NGG 4096
#define NUU 8192
#define KK  6

// ---------------- scratch (device globals, zero-initialized) ----------------
// Replay-safe: rowmin/argmin merges are idempotent atomicMax of identical keys;
// g_knn / g_oripro4 / g_norgt4 are overwritten; g_acc is re-zeroed by k_final.
__device__ float4 g_oripro4[BB*NN];
__device__ float4 g_norgt4[BB*NN];
__device__ unsigned long long g_amin[BB*NN];     // max of (~mono(d)<<32)|~idx
__device__ unsigned long long g_knn[BB*NN*2*KK];
__device__ unsigned g_rm_up_q[BB*NUU];           // max of ~mono(v)
__device__ unsigned g_rm_up_g[BB*NGG];
__device__ unsigned g_rm_of_q[BB*NUU];
__device__ unsigned g_rm_of_g[BB*NGG];
__device__ double g_acc[8];   // 0 loss_nor, 1 loss_nor_ori, 2 smooth, 3 lc, 4 lco

// ---------------- f32x2 helpers (sm_103a packed FMA) ------------------------
__device__ __forceinline__ unsigned long long pk2(float lo, float hi) {
    unsigned long long r;
    asm("mov.b64 %0,{%1,%2};" : "=l"(r) : "f"(lo), "f"(hi));
    return r;
}
__device__ __forceinline__ void upk2(unsigned long long v, float& lo, float& hi) {
    asm("mov.b64 {%0,%1},%2;" : "=f"(lo), "=f"(hi) : "l"(v));
}
__device__ __forceinline__ unsigned long long fma2(unsigned long long a,
                                                   unsigned long long b,
                                                   unsigned long long c) {
    unsigned long long d;
    asm("fma.rn.f32x2 %0,%1,%2,%3;" : "=l"(d) : "l"(a), "l"(b), "l"(c));
    return d;
}
// monotone float->uint (order-preserving incl. negatives)
__device__ __forceinline__ unsigned mono(float f) {
    unsigned u = __float_as_uint(f);
    return u ^ ((unsigned)((int)u >> 31) | 0x80000000u);
}
// inverse for nonneg floats stored as ~mono(v)
__device__ __forceinline__ float un_negmono(unsigned key) {
    return __uint_as_float((~key) ^ 0x80000000u);
}

__device__ __forceinline__ double blockReduceSum(double v) {
    __shared__ double sh[32];
    __syncthreads();
    int lane = threadIdx.x & 31, w = threadIdx.x >> 5;
    #pragma unroll
    for (int o = 16; o; o >>= 1) v += __shfl_down_sync(0xffffffffu, v, o);
    if (lane == 0) sh[w] = v;
    __syncthreads();
    int nw = (blockDim.x + 31) >> 5;
    v = (threadIdx.x < nw) ? sh[threadIdx.x] : 0.0;
    if (w == 0) {
        #pragma unroll
        for (int o = 16; o; o >>= 1) v += __shfl_down_sync(0xffffffffu, v, o);
    }
    return v;
}

// ---------------- fused heavy kernel segments (exact R4 bodies) -------------
__device__ __forceinline__ void seg_knn(const float* __restrict__ pts,
                                        float4* s, int lbid) {
    int b   = lbid / 32;
    int rem = lbid % 32;
    int qc  = rem / 2;
    int ph  = rem % 2;
    for (int j = threadIdx.x; j < 2048; j += 256) {
        const float* tp = pts + (size_t)(b*NN + ph*2048 + j) * 3;
        float x = tp[0], y = tp[1], z = tp[2];
        s[j] = make_float4(-2.f*x, -2.f*y, -2.f*z, fmaf(x, x, fmaf(y, y, z*z)));
    }
    __syncthreads();
    int qi = qc*256 + threadIdx.x;
    const float* p = pts + (size_t)(b*NN + qi) * 3;
    float ax = p[0], ay = p[1], az = p[2];
    float bd[KK];
    int   bi[KK];
    #pragma unroll
    for (int k = 0; k < KK; k++) { bd[k] = 1e30f; bi[k] = 0; }
    #pragma unroll 4
    for (int j = 0; j < 2048; j++) {
        float4 T = s[j];
        float d = fmaf(ax, T.x, fmaf(ay, T.y, fmaf(az, T.z, T.w)));
        if (d < bd[KK-1]) {
            bd[KK-1] = d; bi[KK-1] = ph*2048 + j;
            #pragma unroll
            for (int k = KK-1; k > 0; k--) {
                if (bd[k] < bd[k-1]) {
                    float td = bd[k]; bd[k] = bd[k-1]; bd[k-1] = td;
                    int   ti = bi[k]; bi[k] = bi[k-1]; bi[k-1] = ti;
                }
            }
        }
    }
    unsigned long long* dst = g_knn + ((size_t)(b*NN + qi) * 2 + ph) * KK;
    #pragma unroll
    for (int k = 0; k < KK; k++)
        dst[k] = ((unsigned long long)mono(bd[k]) << 32) | (unsigned)bi[k];
}

// packed f32x2 chamfer: QPT=8, tile=1024, 256 thr
__device__ __forceinline__ void seg_chamfer(const float* __restrict__ q, int nq, int qs,
                                            const float* __restrict__ t, int nt, int ts,
                                            int tsplit, unsigned* rowmin,
                                            char* smem, int lbid) {
    ulonglong2* sxy = (ulonglong2*)smem;            // (m2x,m2x),(m2y,m2y)
    ulonglong2* szs = (ulonglong2*)(smem + 16384);  // (m2z,m2z),(ss,ss)
    const int QPT = 8;
    int qpb = 256 * QPT;               // 2048 queries / block
    int qch = nq / qpb;
    int b   = lbid / (qch * tsplit);
    int rem = lbid % (qch * tsplit);
    int qc  = rem / tsplit;
    int tc  = rem % tsplit;
    int tile  = nt / tsplit;           // == 1024
    int tbase = tc * tile;
    for (int j = threadIdx.x; j < tile; j += 256) {
        const float* tp = t + (size_t)(b*nt + tbase + j) * ts;
        float x = tp[0], y = tp[1], z = tp[2];
        float m2x = -2.f*x, m2y = -2.f*y, m2z = -2.f*z;
        float ss = fmaf(x, x, fmaf(y, y, z*z));
        sxy[j] = make_ulonglong2(pk2(m2x, m2x), pk2(m2y, m2y));
        szs[j] = make_ulonglong2(pk2(m2z, m2z), pk2(ss, ss));
    }
    __syncthreads();
    int qbase = qc * qpb;
    float qx[QPT], qy[QPT], qz[QPT], mn[QPT];
    unsigned long long qx2[QPT/2], qy2[QPT/2], qz2[QPT/2];
    #pragma unroll
    for (int l = 0; l < QPT; l++) {
        int qi = qbase + l*256 + threadIdx.x;
        const float* qp = q + (size_t)(b*nq + qi) * qs;
        qx[l] = qp[0]; qy[l] = qp[1]; qz[l] = qp[2];
        mn[l] = 1e30f;
    }
    #pragma unroll
    for (int p = 0; p < QPT/2; p++) {
        qx2[p] = pk2(qx[2*p], qx[2*p+1]);
        qy2[p] = pk2(qy[2*p], qy[2*p+1]);
        qz2[p] = pk2(qz[2*p], qz[2*p+1]);
    }
    #pragma unroll 2
    for (int j = 0; j < tile; j++) {
        ulonglong2 A = sxy[j];
        ulonglong2 B = szs[j];
        #pragma unroll
        for (int p = 0; p < QPT/2; p++) {
            unsigned long long d = fma2(qz2[p], B.x, B.y);
            d = fma2(qy2[p], A.y, d);
            d = fma2(qx2[p], A.x, d);
            float dl, dh;
            upk2(d, dl, dh);
            mn[2*p]   = fminf(mn[2*p],   dl);
            mn[2*p+1] = fminf(mn[2*p+1], dh);
        }
    }
    #pragma unroll
    for (int l = 0; l < QPT; l++) {
        int qi = qbase + l*256 + threadIdx.x;
        float na = fmaf(qx[l], qx[l], fmaf(qy[l], qy[l], qz[l]*qz[l]));
        float v = fmaxf(mn[l] + na, 0.f);
        atomicMax(&rowmin[b*nq + qi], ~mono(v));
    }
}

__device__ __forceinline__ void seg_argmin(const float* __restrict__ pts,
                                           const float* __restrict__ gt,
                                           float4* s, int lbid) {
    const int TS = 8, QCH = 4;
    int b   = lbid / (QCH*TS);
    int rem = lbid % (QCH*TS);
    int qc  = rem / TS;
    int tc  = rem % TS;
    int tbase = tc * 512;
    for (int j = threadIdx.x; j < 512; j += 256) {
        const float* gp = gt + (size_t)(b*NGG + tbase + j) * 6;
        float x = gp[0], y = gp[1], z = gp[2];
        s[j] = make_float4(-2.f*x, -2.f*y, -2.f*z, fmaf(x, x, fmaf(y, y, z*z)));
    }
    __syncthreads();
    float ax[4], ay[4], az[4], best[4];
    int bi[4];
    int qbase = qc * 1024;
    #pragma unroll
    for (int l = 0; l < 4; l++) {
        int qi = qbase + l*256 + threadIdx.x;
        const float* p = pts + (size_t)(b*NN + qi) * 3;
        ax[l] = p[0]; ay[l] = p[1]; az[l] = p[2];
        best[l] = 1e30f; bi[l] = 0;
    }
    #pragma unroll 2
    for (int j = 0; j < 512; j++) {
        float4 T = s[j];
        #pragma unroll
        for (int l = 0; l < 4; l++) {
            float d = fmaf(ax[l], T.x, fmaf(ay[l], T.y, fmaf(az[l], T.z, T.w)));
            if (d < best[l]) { best[l] = d; bi[l] = tbase + j; }
        }
    }
    #pragma unroll
    for (int l = 0; l < 4; l++) {
        int qi = qbase + l*256 + threadIdx.x;
        unsigned long long key = ((unsigned long long)(~mono(best[l])) << 32)
                               | (unsigned)(~bi[l]);
        atomicMax(&g_amin[b*NN + qi], key);
    }
}

// R4 grouped layout: [0,128) knn | [128,192) up->gt | [192,256) gt->up
// [256,320) off->gt | [320,384) gt->off | [384,512) argmin
__global__ void __launch_bounds__(256) k_heavy(const float* __restrict__ pts,
                                               const float* __restrict__ gt,
                                               const float* __restrict__ up,
                                               const float* __restrict__ off) {
    __shared__ char smem[32768];
    int bid = blockIdx.x;
    if (bid < 128) {
        seg_knn(pts, (float4*)smem, bid);
    } else if (bid < 192) {   // nq=NUU: qch=4, tsplit=4 -> 4*4*4 = 64
        seg_chamfer(up,  NUU, 3, gt,  NGG, 6, 4, g_rm_up_q, smem, bid - 128);
    } else if (bid < 256) {   // nq=NGG: qch=2, tsplit=8 -> 4*2*8 = 64
        seg_chamfer(gt,  NGG, 6, up,  NUU, 3, 8, g_rm_up_g, smem, bid - 192);
    } else if (bid < 320) {
        seg_chamfer(off, NUU, 3, gt,  NGG, 6, 4, g_rm_of_q, smem, bid - 256);
    } else if (bid < 384) {
        seg_chamfer(gt,  NGG, 6, off, NUU, 3, 8, g_rm_of_g, smem, bid - 320);
    } else {
        seg_argmin(pts, gt, (float4*)smem, bid - 384);
    }
}

// per-point: normalize ori/nor inline, gather normal, projection, losses
__global__ void k_post(const float* __restrict__ gt,
                       const float* __restrict__ ori,
                       const float* __restrict__ nor) {
    int i = blockIdx.x * blockDim.x + threadIdx.x;   // 64*256 = 16384 exact
    int b = i / NN;
    unsigned gidx = (~(unsigned)g_amin[i]) & (NGG-1);   // low 32 bits = ~idx
    const float* gp = gt + (size_t)(b*NGG + gidx) * 6;
    float gx = gp[3], gy = gp[4], gz = gp[5];
    float ox = ori[3*i], oy = ori[3*i+1], oz = ori[3*i+2];
    float on = sqrtf(ox*ox + oy*oy + oz*oz + 1e-8f) + 1e-10f;
    ox /= on; oy /= on; oz /= on;
    float dn = fmaf(ox, gx, fmaf(oy, gy, oz*gz));
    float vx = ox - gx*dn, vy = oy - gy*dn, vz = oz - gz*dn;
    float nv = sqrtf(fmaf(vx, vx, fmaf(vy, vy, vz*vz)) + 1e-8f) + 1e-10f;
    g_oripro4[i] = make_float4(vx/nv, vy/nv, vz/nv, 0.f);
    g_norgt4[i]  = make_float4(gx, gy, gz, 0.f);
    float px = nor[3*i], py = nor[3*i+1], pz = nor[3*i+2];
    float pn = sqrtf(px*px + py*py + pz*pz + 1e-8f) + 1e-10f;
    px /= pn; py /= pn; pz /= pn;
    float dpn = fmaf(gx, px, fmaf(gy, py, gz*pz));
    float na = fmaxf(sqrtf(fmaf(gx, gx, fmaf(gy, gy, gz*gz))), 1e-8f);
    float nb = fmaxf(sqrtf(fmaf(px, px, fmaf(py, py, pz*pz))), 1e-8f);
    double s1 = blockReduceSum(1.0 - (double)fabsf(dpn / (na*nb)));
    double s2 = blockReduceSum((double)fabsf(dn));
    if (threadIdx.x == 0) {
        atomicAdd(&g_acc[0], s1);
        atomicAdd(&g_acc[1], s2);
    }
}

// blocks [0,64): smoothness; blocks [64,128): weighted rowmin reduction
__global__ void k_smooth() {
    int bid = blockIdx.x;
    if (bid < 64) {
        int i = bid * blockDim.x + threadIdx.x;     // 0..16383
        int b = i / NN;
        unsigned long long a[2*KK];
        const unsigned long long* src = g_knn + (size_t)i * 2 * KK;
        #pragma unroll
        for (int k = 0; k < 2*KK; k++) a[k] = src[k];
        #pragma unroll
        for (int k = 1; k < 2*KK; k++) {
            unsigned long long v = a[k];
            int m = k;
            while (m > 0 && a[m-1] > v) { a[m] = a[m-1]; m--; }
            a[m] = v;
        }
        int base = b*NN;
        float4 P = g_oripro4[i];
        float4 G = g_norgt4[i];
        float Rx = P.y*G.z - P.z*G.y;
        float Ry = P.z*G.x - P.x*G.z;
        float Rz = P.x*G.y - P.y*G.x;
        float nP = fmaxf(sqrtf(fmaf(P.x, P.x, fmaf(P.y, P.y, P.z*P.z))), 1e-8f);
        float nR = fmaxf(sqrtf(fmaf(Rx, Rx, fmaf(Ry, Ry, Rz*Rz))), 1e-8f);
        double sum = 0.0;
        #pragma unroll
        for (int k = 0; k < KK; k++) {
            int ni = (int)(unsigned)(a[k] & 0xffffffffu);
            float4 go = g_oripro4[base + ni];
            float4 gn = g_norgt4[base + ni];
            float dnn = fmaf(gn.x, G.x, fmaf(gn.y, G.y, gn.z*G.z));
            float ndv = expf(-dnn / 0.3f) * 10.f + 1.f;
            float w = (ndv < 4.f) ? 1.f : 5.f;
            float ngo = fmaxf(sqrtf(fmaf(go.x, go.x, fmaf(go.y, go.y, go.z*go.z))), 1e-8f);
            float c0 = fmaf(go.x, P.x, fmaf(go.y, P.y, go.z*P.z)) / (ngo*nP);
            float c1 = fmaf(go.x, Rx, fmaf(go.y, Ry, go.z*Rz)) / (ngo*nR);
            float c = fminf(1.f - fabsf(c0), 1.f - fabsf(c1));
            sum += (double)(w * c);
        }
        double tot = blockReduceSum(sum);
        if (threadIdx.x == 0) atomicAdd(&g_acc[2], tot);
    } else {
        int i = (bid - 64) * blockDim.x + threadIdx.x;   // 0..16383
        const double wq = 1.0 / (double)(BB*NUU);
        const double wg = 1.0 / (double)(BB*NGG);
        double lc  = wq * ((double)un_negmono(g_rm_up_q[i])
                         + (double)un_negmono(g_rm_up_q[i + 16384]))
                   + wg * (double)un_negmono(g_rm_up_g[i]);
        double lco = wq * ((double)un_negmono(g_rm_of_q[i])
                         + (double)un_negmono(g_rm_of_q[i + 16384]))
                   + wg * (double)un_negmono(g_rm_of_g[i]);
        double s1 = blockReduceSum(lc);
        double s2 = blockReduceSum(lco);
        if (threadIdx.x == 0) {
            atomicAdd(&g_acc[3], s1);
            atomicAdd(&g_acc[4], s2);
        }
    }
}

__global__ void k_final(float* __restrict__ out) {
    if (threadIdx.x == 0) {
        double loss_nor     = g_acc[0] / (double)(BB*NN);
        double loss_nor_ori = g_acc[1] / (double)(BB*NN);
        double loss_smooth  = g_acc[2] / (double)(BB*NN*KK);
        double lc  = g_acc[3];
        double lco = g_acc[4];
        double loss_cd = lc + 0.4 * lco;
        double loss = loss_smooth + loss_nor + 0.1 * loss_nor_ori + 200.0 * loss_cd;
        out[0] = (float)loss;
        out[1] = (float)loss_smooth;
        out[2] = (float)loss_nor;
        out[3] = (float)lco;
        out[4] = (float)loss_nor_ori;
        out[5] = (float)lc;
        out[6] = (float)lc;
        // reset accumulators so every graph replay starts from zero
        #pragma unroll
        for (int k = 0; k < 8; k++) g_acc[k] = 0.0;
    }
}

// ---------------- launch ----------------------------------------------------
extern "C" void kernel_launch(void* const* d_in, const int* in_sizes, int n_in,
                              void* d_out, int out_size) {
    const float* ori = (const float*)d_in[0];
    const float* nor = (const float*)d_in[1];
    const float* up  = (const float*)d_in[2];
    const float* off = (const float*)d_in[3];
    const float* pts = (const float*)d_in[4];
    const float* gt  = (const float*)d_in[5];
    float* out = (float*)d_out;

    k_heavy<<<512, 256>>>(pts, gt, up, off);
    k_post<<<64, 256>>>(gt, ori, nor);
    k_smooth<<<128, 256>>>();
    k_final<<<1, 32>>>(out);
}